// round 2
// baseline (speedup 1.0000x reference)
#include <cuda_runtime.h>
#include <cuda_bf16.h>
#include <math.h>

// Problem constants
#define B_ 256
#define F_ 8
#define S_ 200
#define D_ 64
#define H_ 36
#define BF_ (B_ * F_)   // 2048
#define EPS_ 0.001f

typedef unsigned long long u64;

// ---------------- scratch (device globals; no allocations allowed) ----------
__device__ float g_A[F_ * D_ * H_];    // W1 - W3   [f][d][h]
__device__ float g_Bq[F_ * D_ * H_];   // W2 + W3   [f][d][h]
__device__ float g_h[(size_t)BF_ * S_ * H_];   // 58.98 MB h scratch
__device__ float g_sum[F_ * H_];
__device__ float g_sumsq[F_ * H_];
__device__ float g_mean[F_ * H_];
__device__ float g_rstd[F_ * H_];

// ---------------- packed f32x2 helpers (Blackwell FFMA2) --------------------
__device__ __forceinline__ u64 pack2(float x, float y) {
    u64 r;
    asm("mov.b64 %0, {%1, %2};" : "=l"(r) : "f"(x), "f"(y));
    return r;
}
__device__ __forceinline__ u64 fma2(u64 a, u64 b, u64 c) {
    u64 d;
    asm("fma.rn.f32x2 %0, %1, %2, %3;" : "=l"(d) : "l"(a), "l"(b), "l"(c));
    return d;
}

// ---------------- kernel 0: fold W_h, zero accumulators ---------------------
__global__ void k_prep(const float* __restrict__ Wh) {
    int f = blockIdx.x;
    for (int i = threadIdx.x; i < D_ * H_; i += blockDim.x) {
        int d = i / H_, h = i % H_;
        float w1 = Wh[(f * 3 * D_ + d) * H_ + h];
        float w2 = Wh[(f * 3 * D_ + D_ + d) * H_ + h];
        float w3 = Wh[(f * 3 * D_ + 2 * D_ + d) * H_ + h];
        g_A[f * D_ * H_ + i]  = w1 - w3;
        g_Bq[f * D_ * H_ + i] = w2 + w3;
    }
    if (blockIdx.x == 0) {
        for (int i = threadIdx.x; i < F_ * H_; i += blockDim.x) {
            g_sum[i] = 0.f;
            g_sumsq[i] = 0.f;
        }
    }
}

// ---------------- kernel 1: h = key @ A + (q @ Bq + b_h) --------------------
// one block per (b,f); 128 threads; thread t owns rows s=2t, 2t+1 (t<100)
__device__ __forceinline__ void dstep(const float* A_sm, int d, float k0, float k1,
                                      u64* acc0, u64* acc1) {
    u64 kv0 = pack2(k0, k0);
    u64 kv1 = pack2(k1, k1);
    const ulonglong2* ar = reinterpret_cast<const ulonglong2*>(A_sm + d * H_);
#pragma unroll
    for (int j = 0; j < 9; ++j) {
        ulonglong2 av = ar[j];
        acc0[2 * j]     = fma2(kv0, av.x, acc0[2 * j]);
        acc0[2 * j + 1] = fma2(kv0, av.y, acc0[2 * j + 1]);
        acc1[2 * j]     = fma2(kv1, av.x, acc1[2 * j]);
        acc1[2 * j + 1] = fma2(kv1, av.y, acc1[2 * j + 1]);
    }
}

__global__ __launch_bounds__(128) void k_hgemm(const float* __restrict__ q,
                                               const float* __restrict__ key,
                                               const float* __restrict__ bh) {
    __shared__ __align__(16) float A_sm[D_ * H_];
    __shared__ __align__(16) float c_sm[H_ + 4];
    int bf = blockIdx.x;
    int f = bf & 7;
    int t = threadIdx.x;

    for (int i = t; i < D_ * H_; i += 128) A_sm[i] = g_A[f * D_ * H_ + i];

    if (t < H_) {
        // c0[h] = b_h[f,h] + sum_d q[b,f,d] * Bq[f,d,h]
        const float* qq = q + bf * D_;
        const float* Bq = g_Bq + f * D_ * H_ + t;
        float a0 = 0.f, a1 = 0.f, a2 = 0.f, a3 = 0.f;
#pragma unroll
        for (int d = 0; d < D_; d += 4) {
            a0 += qq[d]     * Bq[d * H_];
            a1 += qq[d + 1] * Bq[(d + 1) * H_];
            a2 += qq[d + 2] * Bq[(d + 2) * H_];
            a3 += qq[d + 3] * Bq[(d + 3) * H_];
        }
        c_sm[t] = bh[f * H_ + t] + ((a0 + a1) + (a2 + a3));
    }
    __syncthreads();

    int tt = (t < 100) ? t : 99;        // keep warps uniform, discard extras
    int s0 = tt * 2;
    const float4* kr0 = reinterpret_cast<const float4*>(key + (size_t)bf * S_ * D_ + (size_t)s0 * D_);
    const float4* kr1 = kr0 + (D_ / 4);

    u64 acc0[18], acc1[18];
#pragma unroll
    for (int j = 0; j < 18; ++j) {
        u64 cp = *reinterpret_cast<const u64*>(&c_sm[2 * j]);
        acc0[j] = cp;
        acc1[j] = cp;
    }

#pragma unroll 2
    for (int dq = 0; dq < 16; ++dq) {
        float4 k0 = kr0[dq];
        float4 k1 = kr1[dq];
        int d = dq * 4;
        dstep(A_sm, d + 0, k0.x, k1.x, acc0, acc1);
        dstep(A_sm, d + 1, k0.y, k1.y, acc0, acc1);
        dstep(A_sm, d + 2, k0.z, k1.z, acc0, acc1);
        dstep(A_sm, d + 3, k0.w, k1.w, acc0, acc1);
    }

    if (t < 100) {
        ulonglong2* o0 = reinterpret_cast<ulonglong2*>(g_h + (size_t)bf * S_ * H_ + (size_t)s0 * H_);
        ulonglong2* o1 = reinterpret_cast<ulonglong2*>(g_h + (size_t)bf * S_ * H_ + (size_t)(s0 + 1) * H_);
#pragma unroll
        for (int j = 0; j < 9; ++j) {
            ulonglong2 v0; v0.x = acc0[2 * j]; v0.y = acc0[2 * j + 1];
            ulonglong2 v1; v1.x = acc1[2 * j]; v1.y = acc1[2 * j + 1];
            o0[j] = v0;
            o1[j] = v1;
        }
    }
}

// ---------------- kernel 2: per-(f,h) sum and sumsq over (b,s) --------------
__global__ __launch_bounds__(288) void k_stats() {
    int bf = blockIdx.x;
    int f = bf & 7;
    int t = threadIdx.x;          // 288 = 36 h * 8 groups
    int h = t % 36, g = t / 36;
    const float* base = g_h + (size_t)bf * S_ * H_;
    float sm = 0.f, sq = 0.f;
#pragma unroll 5
    for (int s = g; s < S_; s += 8) {
        float v = base[s * H_ + h];
        sm += v;
        sq += v * v;
    }
    __shared__ float r1[288], r2[288];
    r1[t] = sm;
    r2[t] = sq;
    __syncthreads();
    if (t < 36) {
        float a = 0.f, b = 0.f;
#pragma unroll
        for (int k = 0; k < 8; ++k) {
            a += r1[t + 36 * k];
            b += r2[t + 36 * k];
        }
        atomicAdd(&g_sum[f * 36 + t], a);
        atomicAdd(&g_sumsq[f * 36 + t], b);
    }
}

// ---------------- kernel 3: finalize mean / rstd ----------------------------
__global__ void k_final() {
    int i = threadIdx.x;
    if (i < F_ * H_) {
        float n = (float)(B_ * S_);
        float m = g_sum[i] / n;
        float v = g_sumsq[i] / n - m * m;
        v = v < 0.f ? 0.f : v;
        g_mean[i] = m;
        g_rstd[i] = rsqrtf(v + EPS_);
    }
}

// ---------------- kernel 4: gate -> scores -> softmax -> attn @ key ---------
__global__ __launch_bounds__(256) void k_attend(const float* __restrict__ key,
                                                const float* __restrict__ alpha,
                                                const float* __restrict__ Wo,
                                                const float* __restrict__ bo,
                                                const int* __restrict__ seq,
                                                float* __restrict__ out) {
    __shared__ float mean_sm[36], rstd_sm[36], wo_sm[36];
    __shared__ float attn_sm[256];
    __shared__ float red[256];
    int bf = blockIdx.x;
    int f = bf & 7;
    int t = threadIdx.x;

    if (t < 36) {
        mean_sm[t] = g_mean[f * 36 + t];
        rstd_sm[t] = g_rstd[f * 36 + t];
        wo_sm[t]   = Wo[f * 36 + t];
    }
    float al = alpha[f];
    float bof = bo[f];
    int n = seq[bf];
    __syncthreads();

    float score = -INFINITY;
    if (t < S_) {
        const float4* hr = reinterpret_cast<const float4*>(g_h + (size_t)bf * S_ * H_ + (size_t)t * H_);
        float sc = 0.f;
#pragma unroll
        for (int j = 0; j < 9; ++j) {
            float4 v = hr[j];
            float xs[4] = {v.x, v.y, v.z, v.w};
#pragma unroll
            for (int k = 0; k < 4; ++k) {
                int h = 4 * j + k;
                float x = xs[k];
                float z = (x - mean_sm[h]) * rstd_sm[h];
                float p = 1.f / (1.f + __expf(-z));
                float gcoef = al * (1.f - p) + p;
                sc += gcoef * x * wo_sm[h];
            }
        }
        score = (t < n) ? (sc + bof) : -INFINITY;
    }

    // block max
    red[t] = score;
    __syncthreads();
#pragma unroll
    for (int off = 128; off >= 1; off >>= 1) {
        if (t < off) red[t] = fmaxf(red[t], red[t + off]);
        __syncthreads();
    }
    float m = red[0];
    __syncthreads();

    float e = __expf(score - m);   // -inf -> 0
    red[t] = e;
    __syncthreads();
#pragma unroll
    for (int off = 128; off >= 1; off >>= 1) {
        if (t < off) red[t] = red[t] + red[t + off];
        __syncthreads();
    }
    float tot = red[0];
    attn_sm[t] = e / tot;          // garbage lanes (t>=200) unused below
    __syncthreads();

    // out[d] = sum_s attn[s] * key[b,f,s,d]
    int d = t & 63;
    int jg = t >> 6;               // 0..3 -> s chunks of 50
    const float* kb = key + (size_t)bf * S_ * D_ + d;
    float acc = 0.f;
#pragma unroll 5
    for (int s = jg * 50; s < jg * 50 + 50; ++s) acc += attn_sm[s] * kb[s * D_];
    red[t] = acc;
    __syncthreads();
    if (t < 64) out[bf * 64 + t] = red[t] + red[t + 64] + red[t + 128] + red[t + 192];
}

// ---------------- launch ----------------------------------------------------
extern "C" void kernel_launch(void* const* d_in, const int* in_sizes, int n_in,
                              void* d_out, int out_size) {
    const float* query = (const float*)d_in[0];
    const float* key   = (const float*)d_in[1];
    const float* W_h   = (const float*)d_in[2];
    const float* b_h   = (const float*)d_in[3];
    const float* alpha = (const float*)d_in[4];
    const float* W_o   = (const float*)d_in[5];
    const float* b_o   = (const float*)d_in[6];
    const int*   seq   = (const int*)d_in[7];
    float* out = (float*)d_out;

    k_prep<<<F_, 256>>>(W_h);
    k_hgemm<<<BF_, 128>>>(query, key, b_h);
    k_stats<<<BF_, 288>>>();
    k_final<<<1, 288>>>();
    k_attend<<<BF_, 256>>>(key, alpha, W_o, b_o, seq, out);
}